// round 1
// baseline (speedup 1.0000x reference)
#include <cuda_runtime.h>

// Problem constants
#define NB   32
#define NS   128
#define NW   4096      // NB*NS independent words
#define CC   32        // chars per word (time steps)
#define HH   256       // hidden
#define G3   768       // 3*H
#define EE   128       // embed dim
#define NV   262       // vocab
#define WPB  16        // words per block
#define BLOCKS_PER_DIR (NW / WPB)   // 256

// Precomputed x-projection table: P[d][v][j] = embed[v] . W_ih[d][j] + b_ih[d][j]
__device__ float g_P[2][NV][G3];

// ---------------------------------------------------------------------------
// Prepack: build the 262x768 per-direction input-projection table.
// Kills the entire x-projection GEMM (vocab is tiny).
// ---------------------------------------------------------------------------
__global__ void prep_p_kernel(const float* __restrict__ embed,
                              const float* __restrict__ Wih_fw,
                              const float* __restrict__ bih_fw,
                              const float* __restrict__ Wih_bw,
                              const float* __restrict__ bih_bw)
{
    __shared__ float ev[EE];
    int v = blockIdx.x;
    int d = blockIdx.y;
    int tid = threadIdx.x;
    if (tid < EE) ev[tid] = embed[(size_t)v * EE + tid];
    __syncthreads();
    const float* W = d ? Wih_bw : Wih_fw;
    const float* b = d ? bih_bw : bih_fw;
#pragma unroll
    for (int m = 0; m < 3; m++) {
        int j = tid + m * 256;
        const float4* wr = reinterpret_cast<const float4*>(W + (size_t)j * EE);
        float acc = 0.f;
#pragma unroll
        for (int e4 = 0; e4 < EE / 4; e4++) {
            float4 wv = wr[e4];
            acc = fmaf(wv.x, ev[4 * e4 + 0], acc);
            acc = fmaf(wv.y, ev[4 * e4 + 1], acc);
            acc = fmaf(wv.z, ev[4 * e4 + 2], acc);
            acc = fmaf(wv.w, ev[4 * e4 + 3], acc);
        }
        g_P[d][v][j] = acc + b[j];
    }
}

// ---------------------------------------------------------------------------
// Activations (accurate enough for 1e-3: __expf ~2ulp, __fdividef ~2ulp)
// ---------------------------------------------------------------------------
__device__ __forceinline__ float sigmoid_f(float x) {
    return __fdividef(1.f, 1.f + __expf(-x));
}
__device__ __forceinline__ float tanh_f(float x) {
    x = fmaxf(-15.f, fminf(15.f, x));      // avoid inf/inf
    float e = __expf(-2.f * x);
    return __fdividef(1.f - e, 1.f + e);
}

// ---------------------------------------------------------------------------
// Main recurrent kernel.
// Block = 16 words x one direction. 256 threads; thread `tid` owns gate
// columns {tid, tid+256, tid+512}, i.e. the full (r,z,n) triple for hidden
// index i = tid -> gate math is thread-local.
// W_hh rows are thread-private -> streamed straight from L2 via float4 LDG
// with 1-deep register prefetch. h is shared via smem (broadcast reads).
// ---------------------------------------------------------------------------
__global__ void __launch_bounds__(256) gru_kernel(
    const int*   __restrict__ chars,       // [NW, CC]
    const int*   __restrict__ chars_mask,  // [NW, CC]
    const int*   __restrict__ data_mask,   // [NW]
    const float* __restrict__ Whh_fw,      // [G3, HH]
    const float* __restrict__ Whh_bw,
    const float* __restrict__ bhh_fw,      // [G3]
    const float* __restrict__ bhh_bw,
    float*       __restrict__ out)         // [NW, 512]
{
    __shared__ float4 hbuf[WPB][HH / 4];   // h state, 16KB
    __shared__ float  bb[G3];              // b_hh, 3KB

    const int tid = threadIdx.x;
    const int d   = blockIdx.y;
    const int n0  = blockIdx.x * WPB;

    const float* __restrict__ W  = d ? Whh_bw : Whh_fw;
    const float* __restrict__ bh = d ? bhh_bw : bhh_fw;

    // init h = 0, stage b_hh
    {
        float4 z4 = make_float4(0.f, 0.f, 0.f, 0.f);
        float4* hb4 = &hbuf[0][0];
#pragma unroll
        for (int q = 0; q < (WPB * HH / 4) / 256; q++)   // 4 stores/thread
            hb4[tid + q * 256] = z4;
        bb[tid]       = bh[tid];
        bb[tid + 256] = bh[tid + 256];
        bb[tid + 512] = bh[tid + 512];
    }
    __syncthreads();

    // this thread's three W_hh rows (r, z, n gates for hidden index tid)
    const float4* __restrict__ w0 = reinterpret_cast<const float4*>(W + (size_t)tid * HH);
    const float4* __restrict__ w1 = reinterpret_cast<const float4*>(W + (size_t)(tid + 256) * HH);
    const float4* __restrict__ w2 = reinterpret_cast<const float4*>(W + (size_t)(tid + 512) * HH);

    for (int step = 0; step < CC; step++) {
        const int t = d ? (CC - 1 - step) : step;

        float accr[WPB], accz[WPB], accn[WPB];
#pragma unroll
        for (int w = 0; w < WPB; w++) { accr[w] = 0.f; accz[w] = 0.f; accn[w] = 0.f; }

        // ---- gh = h @ W_hh^T (K = 256, 4 k's per iter, reg-prefetched) ----
        float4 c0 = __ldg(&w0[0]);
        float4 c1 = __ldg(&w1[0]);
        float4 c2 = __ldg(&w2[0]);
#pragma unroll 2
        for (int kg = 0; kg < HH / 4; kg++) {
            const int kn = (kg + 1 < HH / 4) ? (kg + 1) : (HH / 4 - 1);
            float4 p0 = __ldg(&w0[kn]);
            float4 p1 = __ldg(&w1[kn]);
            float4 p2 = __ldg(&w2[kn]);
#pragma unroll
            for (int w = 0; w < WPB; w++) {
                float4 a = hbuf[w][kg];                 // broadcast LDS.128
                accr[w] = fmaf(a.x, c0.x, accr[w]);
                accr[w] = fmaf(a.y, c0.y, accr[w]);
                accr[w] = fmaf(a.z, c0.z, accr[w]);
                accr[w] = fmaf(a.w, c0.w, accr[w]);
                accz[w] = fmaf(a.x, c1.x, accz[w]);
                accz[w] = fmaf(a.y, c1.y, accz[w]);
                accz[w] = fmaf(a.z, c1.z, accz[w]);
                accz[w] = fmaf(a.w, c1.w, accz[w]);
                accn[w] = fmaf(a.x, c2.x, accn[w]);
                accn[w] = fmaf(a.y, c2.y, accn[w]);
                accn[w] = fmaf(a.z, c2.z, accn[w]);
                accn[w] = fmaf(a.w, c2.w, accn[w]);
            }
            c0 = p0; c1 = p1; c2 = p2;
        }

        // ---- gates (thread-local), update h ----
        __syncthreads();                                 // all h reads done
        float* hb = reinterpret_cast<float*>(hbuf);
#pragma unroll
        for (int w = 0; w < WPB; w++) {
            const int n  = n0 + w;
            const int ch = chars[n * CC + t];
            const int mk = chars_mask[n * CC + t];
            const float* __restrict__ Prow = &g_P[d][ch][0];
            float xr = Prow[tid];
            float xz = Prow[tid + 256];
            float xn = Prow[tid + 512];
            float hold = hb[w * HH + tid];
            float r  = sigmoid_f(xr + bb[tid]       + accr[w]);
            float z  = sigmoid_f(xz + bb[tid + 256] + accz[w]);
            float hn = bb[tid + 512] + accn[w];
            float nn = tanh_f(fmaf(r, hn, xn));
            float hnew = (1.f - z) * nn + z * hold;
            hb[w * HH + tid] = mk ? hnew : hold;         // freeze past seq end
        }
        __syncthreads();                                 // h visible next step
    }

    // ---- final write: out[n, d*256 + i] = h * data_mask[n] ----
    const float* hb = reinterpret_cast<const float*>(hbuf);
#pragma unroll
    for (int w = 0; w < WPB; w++) {
        const int n = n0 + w;
        const float dm = data_mask[n] ? 1.f : 0.f;
        out[(size_t)n * 512 + d * 256 + tid] = hb[w * HH + tid] * dm;
    }
}

// ---------------------------------------------------------------------------
extern "C" void kernel_launch(void* const* d_in, const int* in_sizes, int n_in,
                              void* d_out, int out_size)
{
    const int*   chars      = (const int*)  d_in[0];
    const int*   chars_mask = (const int*)  d_in[1];
    const int*   data_mask  = (const int*)  d_in[2];
    const float* embed      = (const float*)d_in[3];
    const float* Wih_fw     = (const float*)d_in[4];
    const float* Whh_fw     = (const float*)d_in[5];
    const float* bih_fw     = (const float*)d_in[6];
    const float* bhh_fw     = (const float*)d_in[7];
    const float* Wih_bw     = (const float*)d_in[8];
    const float* Whh_bw     = (const float*)d_in[9];
    const float* bih_bw     = (const float*)d_in[10];
    const float* bhh_bw     = (const float*)d_in[11];
    float* out = (float*)d_out;

    prep_p_kernel<<<dim3(NV, 2), 256>>>(embed, Wih_fw, bih_fw, Wih_bw, bih_bw);
    gru_kernel<<<dim3(BLOCKS_PER_DIR, 2), 256>>>(chars, chars_mask, data_mask,
                                                 Whh_fw, Whh_bw, bhh_fw, bhh_bw, out);
}

// round 2
// speedup vs baseline: 1.5456x; 1.5456x over previous
#include <cuda_runtime.h>

// Problem constants
#define NB   32
#define NS   128
#define NW   4096      // NB*NS independent words
#define CC   32        // chars per word (time steps)
#define HH   256       // hidden
#define G3   768       // 3*H
#define EE   128       // embed dim
#define NV   262       // vocab
#define WPB  16        // words per block
#define BLOCKS_PER_DIR (NW / WPB)   // 256

// Precomputed x-projection table: P[d][v][j] = embed[v] . W_ih[d][j] + b_ih[d][j]
// (+ b_hh[j] folded in for the r and z gates, j < 512)
__device__ float g_P[2][NV][G3];
// k-major transposed recurrent weights: g_Wt[d][k][g*256 + j] = W_hh[d][g*256+j][k]
__device__ float g_Wt[2][HH][G3];

// ---------------------------------------------------------------------------
// Prepack 1: input-projection table (kills the x-projection GEMM; vocab=262)
// ---------------------------------------------------------------------------
__global__ void prep_p_kernel(const float* __restrict__ embed,
                              const float* __restrict__ Wih_fw,
                              const float* __restrict__ bih_fw,
                              const float* __restrict__ bhh_fw,
                              const float* __restrict__ Wih_bw,
                              const float* __restrict__ bih_bw,
                              const float* __restrict__ bhh_bw)
{
    __shared__ float ev[EE];
    int v = blockIdx.x;
    int d = blockIdx.y;
    int tid = threadIdx.x;
    if (tid < EE) ev[tid] = embed[(size_t)v * EE + tid];
    __syncthreads();
    const float* W  = d ? Wih_bw : Wih_fw;
    const float* bi = d ? bih_bw : bih_fw;
    const float* bh = d ? bhh_bw : bhh_fw;
#pragma unroll
    for (int m = 0; m < 3; m++) {
        int j = tid + m * 256;
        const float4* wr = reinterpret_cast<const float4*>(W + (size_t)j * EE);
        float acc = 0.f;
#pragma unroll
        for (int e4 = 0; e4 < EE / 4; e4++) {
            float4 wv = wr[e4];
            acc = fmaf(wv.x, ev[4 * e4 + 0], acc);
            acc = fmaf(wv.y, ev[4 * e4 + 1], acc);
            acc = fmaf(wv.z, ev[4 * e4 + 2], acc);
            acc = fmaf(wv.w, ev[4 * e4 + 3], acc);
        }
        acc += bi[j];
        if (m < 2) acc += bh[j];      // fold b_hh into r and z gates only
        g_P[d][v][j] = acc;
    }
}

// ---------------------------------------------------------------------------
// Prepack 2: transpose W_hh to k-major so the recurrent GEMV streams
// coalesced.  Wt[d][k][j] = Whh[d][j][k].
// block = 256 threads over k, blockIdx.x = j (0..767), blockIdx.y = d.
// ---------------------------------------------------------------------------
__global__ void prep_wt_kernel(const float* __restrict__ Whh_fw,
                               const float* __restrict__ Whh_bw)
{
    int j = blockIdx.x;
    int d = blockIdx.y;
    int k = threadIdx.x;
    const float* W = d ? Whh_bw : Whh_fw;
    g_Wt[d][k][j] = W[(size_t)j * HH + k];   // coalesced read, strided write
}

// ---------------------------------------------------------------------------
// Activations (accurate: __expf ~2ulp)
// ---------------------------------------------------------------------------
__device__ __forceinline__ float sigmoid_f(float x) {
    return __fdividef(1.f, 1.f + __expf(-x));
}
__device__ __forceinline__ float tanh_f(float x) {
    x = fmaxf(-15.f, fminf(15.f, x));
    float e = __expf(-2.f * x);
    return __fdividef(1.f - e, 1.f + e);
}

// ---------------------------------------------------------------------------
// Main recurrent kernel.
// Block = 16 words x one direction, 256 threads; thread tid owns the (r,z,n)
// gate triple for hidden index i = tid.  Weights are streamed k-major:
// 3 coalesced LDG.32 per k (1 L1 wavefront each) vs 32-line-splattered
// LDG.128 in R1.  h is shared via smem broadcast reads.
// ---------------------------------------------------------------------------
__global__ void __launch_bounds__(256) gru_kernel(
    const int*   __restrict__ chars,       // [NW, CC]
    const int*   __restrict__ chars_mask,  // [NW, CC]
    const int*   __restrict__ data_mask,   // [NW]
    const float* __restrict__ bhh_fw,      // [G3]
    const float* __restrict__ bhh_bw,
    float*       __restrict__ out)         // [NW, 512]
{
    __shared__ float4 hbuf[WPB][HH / 4];   // h state, 16KB

    const int tid = threadIdx.x;
    const int d   = blockIdx.y;
    const int n0  = blockIdx.x * WPB;

    const float* __restrict__ Wt = &g_Wt[d][0][0];     // [256][768]
    const float  bn = (d ? bhh_bw : bhh_fw)[tid + 512]; // n-gate bias (not foldable)

    // init h = 0
    {
        float4 z4 = make_float4(0.f, 0.f, 0.f, 0.f);
        float4* hb4 = &hbuf[0][0];
#pragma unroll
        for (int q = 0; q < (WPB * HH / 4) / 256; q++)
            hb4[tid + q * 256] = z4;
    }
    __syncthreads();

    for (int step = 0; step < CC; step++) {
        const int t = d ? (CC - 1 - step) : step;

        float accr[WPB], accz[WPB], accn[WPB];
#pragma unroll
        for (int w = 0; w < WPB; w++) { accr[w] = 0.f; accz[w] = 0.f; accn[w] = 0.f; }

        // ---- gh = h @ W_hh^T, k-major coalesced weight stream --------------
        // cur/nxt: 12 scalars = weights for 4 consecutive k, 3 gates.
        float cur[12], nxt[12];
        {
            const float* __restrict__ w0 = Wt + tid;
#pragma unroll
            for (int i = 0; i < 4; i++) {
                cur[3 * i + 0] = __ldg(w0 + (size_t)i * G3);
                cur[3 * i + 1] = __ldg(w0 + (size_t)i * G3 + 256);
                cur[3 * i + 2] = __ldg(w0 + (size_t)i * G3 + 512);
            }
        }
#pragma unroll 2
        for (int kg = 0; kg < HH / 4; kg++) {
            const int kn = (kg + 1 < HH / 4) ? (kg + 1) : kg;
            const float* __restrict__ wN = Wt + (size_t)(4 * kn) * G3 + tid;
#pragma unroll
            for (int i = 0; i < 4; i++) {
                nxt[3 * i + 0] = __ldg(wN + (size_t)i * G3);
                nxt[3 * i + 1] = __ldg(wN + (size_t)i * G3 + 256);
                nxt[3 * i + 2] = __ldg(wN + (size_t)i * G3 + 512);
            }
#pragma unroll
            for (int w = 0; w < WPB; w++) {
                float4 a = hbuf[w][kg];                 // broadcast LDS.128
                accr[w] = fmaf(a.x, cur[0],  accr[w]);
                accz[w] = fmaf(a.x, cur[1],  accz[w]);
                accn[w] = fmaf(a.x, cur[2],  accn[w]);
                accr[w] = fmaf(a.y, cur[3],  accr[w]);
                accz[w] = fmaf(a.y, cur[4],  accz[w]);
                accn[w] = fmaf(a.y, cur[5],  accn[w]);
                accr[w] = fmaf(a.z, cur[6],  accr[w]);
                accz[w] = fmaf(a.z, cur[7],  accz[w]);
                accn[w] = fmaf(a.z, cur[8],  accn[w]);
                accr[w] = fmaf(a.w, cur[9],  accr[w]);
                accz[w] = fmaf(a.w, cur[10], accz[w]);
                accn[w] = fmaf(a.w, cur[11], accn[w]);
            }
#pragma unroll
            for (int i = 0; i < 12; i++) cur[i] = nxt[i];
        }

        // ---- gates (thread-local), update h --------------------------------
        __syncthreads();                                 // all h reads done
        float* hb = reinterpret_cast<float*>(hbuf);
#pragma unroll
        for (int w = 0; w < WPB; w++) {
            const int n  = n0 + w;
            const int ch = chars[n * CC + t];
            const int mk = chars_mask[n * CC + t];
            const float* __restrict__ Prow = &g_P[d][ch][0];
            float xr = Prow[tid];                        // has b_ih + b_hh folded
            float xz = Prow[tid + 256];
            float xn = Prow[tid + 512];                  // b_ih only
            float hold = hb[w * HH + tid];
            float r  = sigmoid_f(xr + accr[w]);
            float z  = sigmoid_f(xz + accz[w]);
            float hn = bn + accn[w];
            float nn = tanh_f(fmaf(r, hn, xn));
            float hnew = (1.f - z) * nn + z * hold;
            hb[w * HH + tid] = mk ? hnew : hold;         // freeze past seq end
        }
        __syncthreads();                                 // h visible next step
    }

    // ---- final write: out[n, d*256 + i] = h * data_mask[n] -----------------
    const float* hb = reinterpret_cast<const float*>(hbuf);
#pragma unroll
    for (int w = 0; w < WPB; w++) {
        const int n = n0 + w;
        const float dm = data_mask[n] ? 1.f : 0.f;
        out[(size_t)n * 512 + d * 256 + tid] = hb[w * HH + tid] * dm;
    }
}

// ---------------------------------------------------------------------------
extern "C" void kernel_launch(void* const* d_in, const int* in_sizes, int n_in,
                              void* d_out, int out_size)
{
    const int*   chars      = (const int*)  d_in[0];
    const int*   chars_mask = (const int*)  d_in[1];
    const int*   data_mask  = (const int*)  d_in[2];
    const float* embed      = (const float*)d_in[3];
    const float* Wih_fw     = (const float*)d_in[4];
    const float* Whh_fw     = (const float*)d_in[5];
    const float* bih_fw     = (const float*)d_in[6];
    const float* bhh_fw     = (const float*)d_in[7];
    const float* Wih_bw     = (const float*)d_in[8];
    const float* Whh_bw     = (const float*)d_in[9];
    const float* bih_bw     = (const float*)d_in[10];
    const float* bhh_bw     = (const float*)d_in[11];
    float* out = (float*)d_out;

    prep_p_kernel<<<dim3(NV, 2), 256>>>(embed, Wih_fw, bih_fw, bhh_fw,
                                        Wih_bw, bih_bw, bhh_bw);
    prep_wt_kernel<<<dim3(G3, 2), HH>>>(Whh_fw, Whh_bw);
    gru_kernel<<<dim3(BLOCKS_PER_DIR, 2), 256>>>(chars, chars_mask, data_mask,
                                                 bhh_fw, bhh_bw, out);
}

// round 3
// speedup vs baseline: 2.0144x; 1.3033x over previous
#include <cuda_runtime.h>

// Problem constants
#define NB   32
#define NS   128
#define NW   4096      // NB*NS independent words
#define CC   32        // chars per word (time steps)
#define HH   256       // hidden
#define G3   768       // 3*H
#define EE   128       // embed dim
#define NV   262       // vocab
#define WPB  16        // words per block
#define HROW 20        // padded smem row (16 words + pad, keeps float4 aligned)
#define BLOCKS_PER_DIR (NW / WPB)   // 256

typedef unsigned long long u64;

// Precomputed x-projection table: P[d][v][j] = embed[v] . W_ih[d][j] + b_ih[d][j]
// (+ b_hh[j] folded in for the r and z gates, j < 512)
__device__ float g_P[2][NV][G3];
// k-major transposed recurrent weights: g_Wt[d][k][g*256 + j] = W_hh[d][g*256+j][k]
__device__ float g_Wt[2][HH][G3];

// ---------------------------------------------------------------------------
// Packed fp32x2 helpers (Blackwell 2x-rate fp32 pipe; ptxas never auto-emits)
// ---------------------------------------------------------------------------
__device__ __forceinline__ void fma2(u64& d, u64 a, u64 b) {
    asm("fma.rn.f32x2 %0, %1, %2, %3;" : "=l"(d) : "l"(a), "l"(b), "l"(d));
}
__device__ __forceinline__ u64 dup2(float x) {
    u64 r;
    asm("mov.b64 %0, {%1, %1};" : "=l"(r) : "f"(x));
    return r;
}

// ---------------------------------------------------------------------------
// Prepack 1: input-projection table (kills the x-projection GEMM; vocab=262)
// ---------------------------------------------------------------------------
__global__ void prep_p_kernel(const float* __restrict__ embed,
                              const float* __restrict__ Wih_fw,
                              const float* __restrict__ bih_fw,
                              const float* __restrict__ bhh_fw,
                              const float* __restrict__ Wih_bw,
                              const float* __restrict__ bih_bw,
                              const float* __restrict__ bhh_bw)
{
    __shared__ float ev[EE];
    int v = blockIdx.x;
    int d = blockIdx.y;
    int tid = threadIdx.x;
    if (tid < EE) ev[tid] = embed[(size_t)v * EE + tid];
    __syncthreads();
    const float* W  = d ? Wih_bw : Wih_fw;
    const float* bi = d ? bih_bw : bih_fw;
    const float* bh = d ? bhh_bw : bhh_fw;
#pragma unroll
    for (int m = 0; m < 3; m++) {
        int j = tid + m * 256;
        const float4* wr = reinterpret_cast<const float4*>(W + (size_t)j * EE);
        float acc = 0.f;
#pragma unroll
        for (int e4 = 0; e4 < EE / 4; e4++) {
            float4 wv = wr[e4];
            acc = fmaf(wv.x, ev[4 * e4 + 0], acc);
            acc = fmaf(wv.y, ev[4 * e4 + 1], acc);
            acc = fmaf(wv.z, ev[4 * e4 + 2], acc);
            acc = fmaf(wv.w, ev[4 * e4 + 3], acc);
        }
        acc += bi[j];
        if (m < 2) acc += bh[j];      // fold b_hh into r and z gates only
        g_P[d][v][j] = acc;
    }
}

// ---------------------------------------------------------------------------
// Prepack 2: transpose W_hh to k-major.  Wt[d][k][j] = Whh[d][j][k].
// ---------------------------------------------------------------------------
__global__ void prep_wt_kernel(const float* __restrict__ Whh_fw,
                               const float* __restrict__ Whh_bw)
{
    int j = blockIdx.x;
    int d = blockIdx.y;
    int k = threadIdx.x;
    const float* W = d ? Whh_bw : Whh_fw;
    g_Wt[d][k][j] = W[(size_t)j * HH + k];
}

// ---------------------------------------------------------------------------
// Activations
// ---------------------------------------------------------------------------
__device__ __forceinline__ float sigmoid_f(float x) {
    return __fdividef(1.f, 1.f + __expf(-x));
}
__device__ __forceinline__ float tanh_f(float x) {
    x = fmaxf(-15.f, fminf(15.f, x));
    float e = __expf(-2.f * x);
    return __fdividef(1.f - e, 1.f + e);
}

// ---------------------------------------------------------------------------
// Main recurrent kernel (packed fp32x2).
// Block = 16 words x one direction, 256 threads; thread tid owns the (r,z,n)
// gate triple for hidden index i = tid.  Words are packed in pairs into the
// f32x2 lanes: h is stored word-major per k (hsm[k][word], row padded to 20),
// so one broadcast LDS.128 feeds two word-pair FFMA2s.  Weights stream
// k-major coalesced from L2 and are dup'd into both lanes (3 movs per k).
// ---------------------------------------------------------------------------
__global__ void __launch_bounds__(256, 2) gru_kernel(
    const int*   __restrict__ chars,       // [NW, CC]
    const int*   __restrict__ chars_mask,  // [NW, CC]
    const int*   __restrict__ data_mask,   // [NW]
    const float* __restrict__ bhh_fw,      // [G3]
    const float* __restrict__ bhh_bw,
    float*       __restrict__ out)         // [NW, 512]
{
    __shared__ float hsm[HH * HROW];       // h[k][word], 20KB

    const int tid = threadIdx.x;
    const int d   = blockIdx.y;
    const int n0  = blockIdx.x * WPB;

    const float* __restrict__ Wt = &g_Wt[d][0][0];      // [256][768]
    const float  bn = (d ? bhh_bw : bhh_fw)[tid + 512]; // n-gate bias

    // init h = 0
#pragma unroll
    for (int q = 0; q < HH * HROW / 256; q++)           // 20 stores/thread
        hsm[tid + q * 256] = 0.f;
    __syncthreads();

    for (int step = 0; step < CC; step++) {
        const int t = d ? (CC - 1 - step) : step;

        // accumulators: 8 word-pairs x 3 gates, packed fp32x2
        u64 accr[WPB / 2], accz[WPB / 2], accn[WPB / 2];
#pragma unroll
        for (int p = 0; p < WPB / 2; p++) { accr[p] = 0ull; accz[p] = 0ull; accn[p] = 0ull; }

        // ---- gh = h @ W_hh^T; 4 k per iter, weights prefetched -------------
        float cur[12], nxt[12];
        {
            const float* __restrict__ w0 = Wt + tid;
#pragma unroll
            for (int i = 0; i < 4; i++) {
                cur[3 * i + 0] = __ldg(w0 + (size_t)i * G3);
                cur[3 * i + 1] = __ldg(w0 + (size_t)i * G3 + 256);
                cur[3 * i + 2] = __ldg(w0 + (size_t)i * G3 + 512);
            }
        }
#pragma unroll 2
        for (int kg = 0; kg < HH / 4; kg++) {
            const int kn = (kg + 1 < HH / 4) ? (kg + 1) : kg;
            const float* __restrict__ wN = Wt + (size_t)(4 * kn) * G3 + tid;
#pragma unroll
            for (int i = 0; i < 4; i++) {
                nxt[3 * i + 0] = __ldg(wN + (size_t)i * G3);
                nxt[3 * i + 1] = __ldg(wN + (size_t)i * G3 + 256);
                nxt[3 * i + 2] = __ldg(wN + (size_t)i * G3 + 512);
            }
#pragma unroll
            for (int i = 0; i < 4; i++) {
                const int k = 4 * kg + i;
                const u64 wr2 = dup2(cur[3 * i + 0]);
                const u64 wz2 = dup2(cur[3 * i + 1]);
                const u64 wn2 = dup2(cur[3 * i + 2]);
                const ulonglong2* __restrict__ hk =
                    reinterpret_cast<const ulonglong2*>(&hsm[k * HROW]);
#pragma unroll
                for (int q = 0; q < WPB / 4; q++) {      // 4 LDS.128 broadcast
                    ulonglong2 a = hk[q];                // words 4q..4q+3
                    fma2(accr[2 * q],     a.x, wr2);
                    fma2(accz[2 * q],     a.x, wz2);
                    fma2(accn[2 * q],     a.x, wn2);
                    fma2(accr[2 * q + 1], a.y, wr2);
                    fma2(accz[2 * q + 1], a.y, wz2);
                    fma2(accn[2 * q + 1], a.y, wn2);
                }
            }
#pragma unroll
            for (int i = 0; i < 12; i++) cur[i] = nxt[i];
        }

        // ---- gates (thread-local), update h --------------------------------
        __syncthreads();                                 // all h reads done
        const float* ar = reinterpret_cast<const float*>(accr);
        const float* az = reinterpret_cast<const float*>(accz);
        const float* an = reinterpret_cast<const float*>(accn);
#pragma unroll
        for (int w = 0; w < WPB; w++) {
            const int n  = n0 + w;
            const int ch = chars[n * CC + t];
            const int mk = chars_mask[n * CC + t];
            const float* __restrict__ Prow = &g_P[d][ch][0];
            float xr = Prow[tid];                        // b_ih + b_hh folded
            float xz = Prow[tid + 256];
            float xn = Prow[tid + 512];                  // b_ih only
            float hold = hsm[tid * HROW + w];
            float r  = sigmoid_f(xr + ar[w]);
            float z  = sigmoid_f(xz + az[w]);
            float hn = bn + an[w];
            float nn = tanh_f(fmaf(r, hn, xn));
            float hnew = (1.f - z) * nn + z * hold;
            hsm[tid * HROW + w] = mk ? hnew : hold;      // freeze past seq end
        }
        __syncthreads();                                 // h visible next step
    }

    // ---- final write: out[n, d*256 + i] = h * data_mask[n] -----------------
#pragma unroll
    for (int w = 0; w < WPB; w++) {
        const int n = n0 + w;
        const float dm = data_mask[n] ? 1.f : 0.f;
        out[(size_t)n * 512 + d * 256 + tid] = hsm[tid * HROW + w] * dm;
    }
}

// ---------------------------------------------------------------------------
extern "C" void kernel_launch(void* const* d_in, const int* in_sizes, int n_in,
                              void* d_out, int out_size)
{
    const int*   chars      = (const int*)  d_in[0];
    const int*   chars_mask = (const int*)  d_in[1];
    const int*   data_mask  = (const int*)  d_in[2];
    const float* embed      = (const float*)d_in[3];
    const float* Wih_fw     = (const float*)d_in[4];
    const float* Whh_fw     = (const float*)d_in[5];
    const float* bih_fw     = (const float*)d_in[6];
    const float* bhh_fw     = (const float*)d_in[7];
    const float* Wih_bw     = (const float*)d_in[8];
    const float* Whh_bw     = (const float*)d_in[9];
    const float* bih_bw     = (const float*)d_in[10];
    const float* bhh_bw     = (const float*)d_in[11];
    float* out = (float*)d_out;

    prep_p_kernel<<<dim3(NV, 2), 256>>>(embed, Wih_fw, bih_fw, bhh_fw,
                                        Wih_bw, bih_bw, bhh_bw);
    prep_wt_kernel<<<dim3(G3, 2), HH>>>(Whh_fw, Whh_bw);
    gru_kernel<<<dim3(BLOCKS_PER_DIR, 2), 256>>>(chars, chars_mask, data_mask,
                                                 bhh_fw, bhh_bw, out);
}

// round 4
// speedup vs baseline: 2.0147x; 1.0002x over previous
#include <cuda_runtime.h>

// Problem constants
#define NB   32
#define NS   128
#define NW   4096      // NB*NS independent words
#define CC   32        // chars per word (time steps)
#define HH   256       // hidden
#define G3   768       // 3*H
#define EE   128       // embed dim
#define NV   262       // vocab
#define WPB  16        // words per block
#define HROW 20        // padded smem row (16 words + pad, keeps float4 aligned)
#define BLOCKS_PER_DIR (NW / WPB)   // 256

typedef unsigned long long u64;

// Precomputed x-projection table: P[d][v][j] = embed[v] . W_ih[d][j] + b_ih[d][j]
// (+ b_hh[j] folded in for the r and z gates, j < 512)
__device__ float g_P[2][NV][G3];
// k-major transposed recurrent weights: g_Wt[d][k][g*256 + j] = W_hh[d][g*256+j][k]
__device__ float g_Wt[2][HH][G3];

// ---------------------------------------------------------------------------
// Packed fp32x2 helpers (Blackwell 2x-rate fp32 pipe; ptxas never auto-emits)
// ---------------------------------------------------------------------------
__device__ __forceinline__ void fma2(u64& d, u64 a, u64 b) {
    asm("fma.rn.f32x2 %0, %1, %2, %3;" : "=l"(d) : "l"(a), "l"(b), "l"(d));
}
__device__ __forceinline__ u64 dup2(float x) {
    u64 r;
    asm("mov.b64 %0, {%1, %1};" : "=l"(r) : "f"(x));
    return r;
}

// ---------------------------------------------------------------------------
// Prepack 1: input-projection table (kills the x-projection GEMM; vocab=262)
// ---------------------------------------------------------------------------
__global__ void prep_p_kernel(const float* __restrict__ embed,
                              const float* __restrict__ Wih_fw,
                              const float* __restrict__ bih_fw,
                              const float* __restrict__ bhh_fw,
                              const float* __restrict__ Wih_bw,
                              const float* __restrict__ bih_bw,
                              const float* __restrict__ bhh_bw)
{
    __shared__ float ev[EE];
    int v = blockIdx.x;
    int d = blockIdx.y;
    int tid = threadIdx.x;
    if (tid < EE) ev[tid] = embed[(size_t)v * EE + tid];
    __syncthreads();
    const float* W  = d ? Wih_bw : Wih_fw;
    const float* bi = d ? bih_bw : bih_fw;
    const float* bh = d ? bhh_bw : bhh_fw;
#pragma unroll
    for (int m = 0; m < 3; m++) {
        int j = tid + m * 256;
        const float4* wr = reinterpret_cast<const float4*>(W + (size_t)j * EE);
        float acc = 0.f;
#pragma unroll
        for (int e4 = 0; e4 < EE / 4; e4++) {
            float4 wv = wr[e4];
            acc = fmaf(wv.x, ev[4 * e4 + 0], acc);
            acc = fmaf(wv.y, ev[4 * e4 + 1], acc);
            acc = fmaf(wv.z, ev[4 * e4 + 2], acc);
            acc = fmaf(wv.w, ev[4 * e4 + 3], acc);
        }
        acc += bi[j];
        if (m < 2) acc += bh[j];      // fold b_hh into r and z gates only
        g_P[d][v][j] = acc;
    }
}

// ---------------------------------------------------------------------------
// Prepack 2: transpose W_hh to k-major.  Wt[d][k][j] = Whh[d][j][k].
// ---------------------------------------------------------------------------
__global__ void prep_wt_kernel(const float* __restrict__ Whh_fw,
                               const float* __restrict__ Whh_bw)
{
    int j = blockIdx.x;
    int d = blockIdx.y;
    int k = threadIdx.x;
    const float* W = d ? Whh_bw : Whh_fw;
    g_Wt[d][k][j] = W[(size_t)j * HH + k];
}

// ---------------------------------------------------------------------------
// Activations
// ---------------------------------------------------------------------------
__device__ __forceinline__ float sigmoid_f(float x) {
    return __fdividef(1.f, 1.f + __expf(-x));
}
__device__ __forceinline__ float tanh_f(float x) {
    x = fmaxf(-15.f, fminf(15.f, x));
    float e = __expf(-2.f * x);
    return __fdividef(1.f - e, 1.f + e);
}

// ---------------------------------------------------------------------------
// Main recurrent kernel (packed fp32x2).
// Block = 16 words x one direction, 256 threads; thread tid owns the (r,z,n)
// gate triple for hidden index i = tid.  Words are packed in pairs into the
// f32x2 lanes: h is stored word-major per k (hsm[k][word], row padded to 20),
// so one broadcast LDS.128 feeds two word-pair FFMA2s.  Weights stream
// k-major coalesced from L2 and are dup'd into both lanes (3 movs per k).
// ---------------------------------------------------------------------------
__global__ void __launch_bounds__(256, 2) gru_kernel(
    const int*   __restrict__ chars,       // [NW, CC]
    const int*   __restrict__ chars_mask,  // [NW, CC]
    const int*   __restrict__ data_mask,   // [NW]
    const float* __restrict__ bhh_fw,      // [G3]
    const float* __restrict__ bhh_bw,
    float*       __restrict__ out)         // [NW, 512]
{
    __shared__ float hsm[HH * HROW];       // h[k][word], 20KB

    const int tid = threadIdx.x;
    const int d   = blockIdx.y;
    const int n0  = blockIdx.x * WPB;

    const float* __restrict__ Wt = &g_Wt[d][0][0];      // [256][768]
    const float  bn = (d ? bhh_bw : bhh_fw)[tid + 512]; // n-gate bias

    // init h = 0
#pragma unroll
    for (int q = 0; q < HH * HROW / 256; q++)           // 20 stores/thread
        hsm[tid + q * 256] = 0.f;
    __syncthreads();

    for (int step = 0; step < CC; step++) {
        const int t = d ? (CC - 1 - step) : step;

        // accumulators: 8 word-pairs x 3 gates, packed fp32x2
        u64 accr[WPB / 2], accz[WPB / 2], accn[WPB / 2];
#pragma unroll
        for (int p = 0; p < WPB / 2; p++) { accr[p] = 0ull; accz[p] = 0ull; accn[p] = 0ull; }

        // ---- gh = h @ W_hh^T; 4 k per iter, weights prefetched -------------
        float cur[12], nxt[12];
        {
            const float* __restrict__ w0 = Wt + tid;
#pragma unroll
            for (int i = 0; i < 4; i++) {
                cur[3 * i + 0] = __ldg(w0 + (size_t)i * G3);
                cur[3 * i + 1] = __ldg(w0 + (size_t)i * G3 + 256);
                cur[3 * i + 2] = __ldg(w0 + (size_t)i * G3 + 512);
            }
        }
#pragma unroll 2
        for (int kg = 0; kg < HH / 4; kg++) {
            const int kn = (kg + 1 < HH / 4) ? (kg + 1) : kg;
            const float* __restrict__ wN = Wt + (size_t)(4 * kn) * G3 + tid;
#pragma unroll
            for (int i = 0; i < 4; i++) {
                nxt[3 * i + 0] = __ldg(wN + (size_t)i * G3);
                nxt[3 * i + 1] = __ldg(wN + (size_t)i * G3 + 256);
                nxt[3 * i + 2] = __ldg(wN + (size_t)i * G3 + 512);
            }
#pragma unroll
            for (int i = 0; i < 4; i++) {
                const int k = 4 * kg + i;
                const u64 wr2 = dup2(cur[3 * i + 0]);
                const u64 wz2 = dup2(cur[3 * i + 1]);
                const u64 wn2 = dup2(cur[3 * i + 2]);
                const ulonglong2* __restrict__ hk =
                    reinterpret_cast<const ulonglong2*>(&hsm[k * HROW]);
#pragma unroll
                for (int q = 0; q < WPB / 4; q++) {      // 4 LDS.128 broadcast
                    ulonglong2 a = hk[q];                // words 4q..4q+3
                    fma2(accr[2 * q],     a.x, wr2);
                    fma2(accz[2 * q],     a.x, wz2);
                    fma2(accn[2 * q],     a.x, wn2);
                    fma2(accr[2 * q + 1], a.y, wr2);
                    fma2(accz[2 * q + 1], a.y, wz2);
                    fma2(accn[2 * q + 1], a.y, wn2);
                }
            }
#pragma unroll
            for (int i = 0; i < 12; i++) cur[i] = nxt[i];
        }

        // ---- gates (thread-local), update h --------------------------------
        __syncthreads();                                 // all h reads done
        const float* ar = reinterpret_cast<const float*>(accr);
        const float* az = reinterpret_cast<const float*>(accz);
        const float* an = reinterpret_cast<const float*>(accn);
#pragma unroll
        for (int w = 0; w < WPB; w++) {
            const int n  = n0 + w;
            const int ch = chars[n * CC + t];
            const int mk = chars_mask[n * CC + t];
            const float* __restrict__ Prow = &g_P[d][ch][0];
            float xr = Prow[tid];                        // b_ih + b_hh folded
            float xz = Prow[tid + 256];
            float xn = Prow[tid + 512];                  // b_ih only
            float hold = hsm[tid * HROW + w];
            float r  = sigmoid_f(xr + ar[w]);
            float z  = sigmoid_f(xz + az[w]);
            float hn = bn + an[w];
            float nn = tanh_f(fmaf(r, hn, xn));
            float hnew = (1.f - z) * nn + z * hold;
            hsm[tid * HROW + w] = mk ? hnew : hold;      // freeze past seq end
        }
        __syncthreads();                                 // h visible next step
    }

    // ---- final write: out[n, d*256 + i] = h * data_mask[n] -----------------
#pragma unroll
    for (int w = 0; w < WPB; w++) {
        const int n = n0 + w;
        const float dm = data_mask[n] ? 1.f : 0.f;
        out[(size_t)n * 512 + d * 256 + tid] = hsm[tid * HROW + w] * dm;
    }
}

// ---------------------------------------------------------------------------
extern "C" void kernel_launch(void* const* d_in, const int* in_sizes, int n_in,
                              void* d_out, int out_size)
{
    const int*   chars      = (const int*)  d_in[0];
    const int*   chars_mask = (const int*)  d_in[1];
    const int*   data_mask  = (const int*)  d_in[2];
    const float* embed      = (const float*)d_in[3];
    const float* Wih_fw     = (const float*)d_in[4];
    const float* Whh_fw     = (const float*)d_in[5];
    const float* bih_fw     = (const float*)d_in[6];
    const float* bhh_fw     = (const float*)d_in[7];
    const float* Wih_bw     = (const float*)d_in[8];
    const float* Whh_bw     = (const float*)d_in[9];
    const float* bih_bw     = (const float*)d_in[10];
    const float* bhh_bw     = (const float*)d_in[11];
    float* out = (float*)d_out;

    prep_p_kernel<<<dim3(NV, 2), 256>>>(embed, Wih_fw, bih_fw, bhh_fw,
                                        Wih_bw, bih_bw, bhh_bw);
    prep_wt_kernel<<<dim3(G3, 2), HH>>>(Whh_fw, Whh_bw);
    gru_kernel<<<dim3(BLOCKS_PER_DIR, 2), 256>>>(chars, chars_mask, data_mask,
                                                 bhh_fw, bhh_bw, out);
}